// round 11
// baseline (speedup 1.0000x reference)
#include <cuda_runtime.h>
#include <math.h>
#include <stdint.h>

#define MAX_ATOMS 50000

__device__ float g_dEdD[MAX_ATOMS * 64];

// ---- smem byte-offset map (weights only, ~141 KB) ----
#define OB_W1B  0         // [t=128][dpair<32]  stride 36 u2 : B of GEMM1
#define OB_W2B  36864     // [j=64][tpair<64]   stride 68 u2 : B of GEMM2
#define OB_W2TB 71680     // [t=128][jpair<32]  stride 36 u2 : B of GEMM3
#define OB_W1TB 108544    // [d=64][tpair<64]   stride 68 u2 : B of GEMM4
#define OB_B1   143360
#define OB_B2   143872
#define OB_W3   144128
#define SMEM_BYTES 144384

// m16n8k16 bf16 mma, fp32 accumulate, D==C in place
__device__ __forceinline__ void mma16(float* d,
                                      uint32_t a0, uint32_t a1, uint32_t a2, uint32_t a3,
                                      uint32_t b0, uint32_t b1) {
    asm("mma.sync.aligned.m16n8k16.row.col.f32.bf16.bf16.f32 "
        "{%0,%1,%2,%3}, {%4,%5,%6,%7}, {%8,%9}, {%0,%1,%2,%3};"
        : "+f"(d[0]), "+f"(d[1]), "+f"(d[2]), "+f"(d[3])
        : "r"(a0), "r"(a1), "r"(a2), "r"(a3), "r"(b0), "r"(b1));
}
// split pair (v0,v1) -> bf16x2 hi pack + bf16x2 lo pack; v = hi + lo
__device__ __forceinline__ void split_pair(float v0, float v1,
                                           uint32_t& hi, uint32_t& lo) {
    uint32_t h;
    asm("cvt.rn.bf16x2.f32 %0, %1, %2;" : "=r"(h) : "f"(v1), "f"(v0));
    float h0 = __uint_as_float(h << 16);
    float h1 = __uint_as_float(h & 0xffff0000u);
    asm("cvt.rn.bf16x2.f32 %0, %1, %2;" : "=r"(lo) : "f"(v1 - h1), "f"(v0 - h0));
    hi = h;
}
__device__ __forceinline__ float bf_lo(uint32_t p) { return __uint_as_float(p << 16); }
__device__ __forceinline__ float bf_hi(uint32_t p) { return __uint_as_float(p & 0xffff0000u); }

// branch-free tanh: 1 - 2/(e^{2x}+1). 2 MUFU + FMA, err ~1e-7.
__device__ __forceinline__ float fast_tanh(float x) {
    float e, r;
    asm("ex2.approx.f32 %0, %1;" : "=f"(e) : "f"(x * 2.8853900817779268f));
    asm("rcp.approx.f32 %0, %1;" : "=f"(r) : "f"(e + 1.0f));
    return fmaf(-2.f, r, 1.f);
}

// ---------------------------------------------------------------------------
// MLP fwd+bwd on bf16 tensor cores, fully register-resident activations.
// The m16n8k16 D-fragment layout (cols {8nt+2t,8nt+2t+1}, rows {g,g+8})
// IS the A-fragment layout of the next GEMM (k-tile s needs nt=2s,2s+1 from
// the same thread), so h1/d2/g1 never touch shared memory.
// 256 thr = 8 autonomous warps; 16 atoms/warp/chunk, grid-stride.
// ---------------------------------------------------------------------------
__global__ void __launch_bounds__(256, 1)
mlp_kernel(const float* __restrict__ x, const int* __restrict__ indices,
           const float* __restrict__ W1, const float* __restrict__ b1,
           const float* __restrict__ W2, const float* __restrict__ b2,
           const float* __restrict__ W3, const float* __restrict__ b3,
           float* __restrict__ energy, int natoms)
{
    extern __shared__ char smraw[];
    uint2* W1B  = (uint2*)(smraw + OB_W1B);
    uint2* W2B  = (uint2*)(smraw + OB_W2B);
    uint2* W2TB = (uint2*)(smraw + OB_W2TB);
    uint2* W1TB = (uint2*)(smraw + OB_W1TB);
    float* b1s  = (float*)(smraw + OB_B1);
    float* b2s  = (float*)(smraw + OB_B2);
    float* w3s  = (float*)(smraw + OB_W3);

    const int tid  = threadIdx.x;
    const int wid  = tid >> 5;
    const int lane = tid & 31;

    // ---- stage weights: {hi,lo} bf16x2 packs, 4 layouts ----
    for (int i = tid; i < 128 * 32; i += 256) {       // W1B [t][dpair]
        int t = i >> 5, dp = i & 31;
        uint32_t hi, lo;
        split_pair(W1[(2 * dp) * 128 + t], W1[(2 * dp + 1) * 128 + t], hi, lo);
        W1B[t * 36 + dp] = make_uint2(hi, lo);
    }
    for (int i = tid; i < 64 * 64; i += 256) {        // W2B [j][tpair]
        int j = i >> 6, tp = i & 63;
        uint32_t hi, lo;
        split_pair(W2[(2 * tp) * 64 + j], W2[(2 * tp + 1) * 64 + j], hi, lo);
        W2B[j * 68 + tp] = make_uint2(hi, lo);
    }
    for (int i = tid; i < 128 * 32; i += 256) {       // W2TB [t][jpair]
        int t = i >> 5, jp = i & 31;
        uint32_t hi, lo;
        split_pair(W2[t * 64 + 2 * jp], W2[t * 64 + 2 * jp + 1], hi, lo);
        W2TB[t * 36 + jp] = make_uint2(hi, lo);
    }
    for (int i = tid; i < 64 * 64; i += 256) {        // W1TB [d][tpair]
        int d = i >> 6, tp = i & 63;
        uint32_t hi, lo;
        split_pair(W1[d * 128 + 2 * tp], W1[d * 128 + 2 * tp + 1], hi, lo);
        W1TB[d * 68 + tp] = make_uint2(hi, lo);
    }
    if (tid < 128) b1s[tid] = b1[tid];
    if (tid < 64)  { b2s[tid] = b2[tid]; w3s[tid] = W3[tid]; }
    const float b3v = b3[0];
    __syncthreads();

    const int g = lane >> 2;     // groupID 0..7
    const int t = lane & 3;      // threadID in group

    const int gwarp  = blockIdx.x * 8 + wid;
    const int nwarps = gridDim.x * 8;
    const int nchunk = (natoms + 15) >> 4;
    const float2* x2 = (const float2*)x;

    for (int chunk = gwarp; chunk < nchunk; chunk += nwarps) {
        const int base = chunk << 4;
        const int r0 = base + g, r1 = base + g + 8;
        const bool ok0 = r0 < natoms, ok1 = r1 < natoms;

        // h1 / g1 register packs: [nt]: rows g (h0*) and g+8 (h1*)
        uint32_t h0h[16], h0l[16], h1h[16], h1l[16];

        // ========== GEMM1: H1pre = X @ W1  (N=128, K=64) ==================
        {
            float acc[16][4];
            #pragma unroll
            for (int nt = 0; nt < 16; nt++)
                #pragma unroll
                for (int q = 0; q < 4; q++) acc[nt][q] = 0.f;

            #pragma unroll
            for (int s = 0; s < 4; s++) {
                float2 z = make_float2(0.f, 0.f);
                float2 v00 = ok0 ? __ldg(x2 + (size_t)r0 * 32 + 8 * s + t)     : z;
                float2 v01 = ok0 ? __ldg(x2 + (size_t)r0 * 32 + 8 * s + t + 4) : z;
                float2 v10 = ok1 ? __ldg(x2 + (size_t)r1 * 32 + 8 * s + t)     : z;
                float2 v11 = ok1 ? __ldg(x2 + (size_t)r1 * 32 + 8 * s + t + 4) : z;
                uint32_t a0h, a0l, a1h, a1l, a2h, a2l, a3h, a3l;
                split_pair(v00.x, v00.y, a0h, a0l);
                split_pair(v10.x, v10.y, a1h, a1l);
                split_pair(v01.x, v01.y, a2h, a2l);
                split_pair(v11.x, v11.y, a3h, a3l);
                #pragma unroll
                for (int nt = 0; nt < 16; nt++) {
                    uint2 B0 = W1B[(8 * nt + g) * 36 + 8 * s + t];
                    uint2 B1 = W1B[(8 * nt + g) * 36 + 8 * s + t + 4];
                    mma16(acc[nt], a0h, a1h, a2h, a3h, B0.x, B1.x);
                    mma16(acc[nt], a0l, a1l, a2l, a3l, B0.x, B1.x);
                    mma16(acc[nt], a0h, a1h, a2h, a3h, B0.y, B1.y);
                }
            }
            // epi1: h1 = tanh(.+b1) -> register packs
            #pragma unroll
            for (int nt = 0; nt < 16; nt++) {
                int c = 8 * nt + 2 * t;
                float2 bb = *(const float2*)(b1s + c);
                split_pair(fast_tanh(acc[nt][0] + bb.x),
                           fast_tanh(acc[nt][1] + bb.y), h0h[nt], h0l[nt]);
                split_pair(fast_tanh(acc[nt][2] + bb.x),
                           fast_tanh(acc[nt][3] + bb.y), h1h[nt], h1l[nt]);
            }
        }

        // ========== GEMM2: H2pre = H1 @ W2 (N=64, K=128) ==================
        float d2v[8][4];
        float e0 = 0.f, e1 = 0.f;
        {
            float ac2[8][4];
            #pragma unroll
            for (int nt = 0; nt < 8; nt++)
                #pragma unroll
                for (int q = 0; q < 4; q++) ac2[nt][q] = 0.f;

            #pragma unroll
            for (int s = 0; s < 8; s++) {
                uint32_t A0h = h0h[2 * s],     A0l = h0l[2 * s];
                uint32_t A1h = h1h[2 * s],     A1l = h1l[2 * s];
                uint32_t A2h = h0h[2 * s + 1], A2l = h0l[2 * s + 1];
                uint32_t A3h = h1h[2 * s + 1], A3l = h1l[2 * s + 1];
                #pragma unroll
                for (int nt = 0; nt < 8; nt++) {
                    uint2 B0 = W2B[(8 * nt + g) * 68 + 8 * s + t];
                    uint2 B1 = W2B[(8 * nt + g) * 68 + 8 * s + t + 4];
                    mma16(ac2[nt], A0h, A1h, A2h, A3h, B0.x, B1.x);
                    mma16(ac2[nt], A0l, A1l, A2l, A3l, B0.x, B1.x);
                    mma16(ac2[nt], A0h, A1h, A2h, A3h, B0.y, B1.y);
                }
            }
            // epi2: h2 = tanh(.+b2); energy; d2 = w3*(1-h2^2)
            #pragma unroll
            for (int nt = 0; nt < 8; nt++) {
                int c = 8 * nt + 2 * t;
                float2 bb = *(const float2*)(b2s + c);
                float2 w3 = *(const float2*)(w3s + c);
                float h0 = fast_tanh(ac2[nt][0] + bb.x);
                float h1v = fast_tanh(ac2[nt][1] + bb.y);
                float h2v = fast_tanh(ac2[nt][2] + bb.x);
                float h3v = fast_tanh(ac2[nt][3] + bb.y);
                e0 += h0 * w3.x + h1v * w3.y;
                e1 += h2v * w3.x + h3v * w3.y;
                d2v[nt][0] = w3.x * (1.f - h0 * h0);
                d2v[nt][1] = w3.y * (1.f - h1v * h1v);
                d2v[nt][2] = w3.x * (1.f - h2v * h2v);
                d2v[nt][3] = w3.y * (1.f - h3v * h3v);
            }
        }
        e0 += __shfl_xor_sync(0xffffffffu, e0, 1);
        e0 += __shfl_xor_sync(0xffffffffu, e0, 2);
        e1 += __shfl_xor_sync(0xffffffffu, e1, 1);
        e1 += __shfl_xor_sync(0xffffffffu, e1, 2);
        if (t == 0) {
            if (ok0) atomicAdd(&energy[__ldg(indices + r0)], e0 + b3v);
            if (ok1) atomicAdd(&energy[__ldg(indices + r1)], e1 + b3v);
        }

        // ========== GEMM3: G1pre = D2 @ W2^T (N=128, K=64) ================
        {
            float ac3[16][4];
            #pragma unroll
            for (int nt = 0; nt < 16; nt++)
                #pragma unroll
                for (int q = 0; q < 4; q++) ac3[nt][q] = 0.f;

            #pragma unroll
            for (int s = 0; s < 4; s++) {
                uint32_t a0h, a0l, a1h, a1l, a2h, a2l, a3h, a3l;
                split_pair(d2v[2 * s][0],     d2v[2 * s][1],     a0h, a0l);
                split_pair(d2v[2 * s][2],     d2v[2 * s][3],     a1h, a1l);
                split_pair(d2v[2 * s + 1][0], d2v[2 * s + 1][1], a2h, a2l);
                split_pair(d2v[2 * s + 1][2], d2v[2 * s + 1][3], a3h, a3l);
                #pragma unroll
                for (int nt = 0; nt < 16; nt++) {
                    uint2 B0 = W2TB[(8 * nt + g) * 36 + 8 * s + t];
                    uint2 B1 = W2TB[(8 * nt + g) * 36 + 8 * s + t + 4];
                    mma16(ac3[nt], a0h, a1h, a2h, a3h, B0.x, B1.x);
                    mma16(ac3[nt], a0l, a1l, a2l, a3l, B0.x, B1.x);
                    mma16(ac3[nt], a0h, a1h, a2h, a3h, B0.y, B1.y);
                }
            }
            // epi3: g1 = G1pre * (1 - h1^2) -> overwrite h1 register packs
            #pragma unroll
            for (int nt = 0; nt < 16; nt++) {
                float h00 = bf_lo(h0h[nt]) + bf_lo(h0l[nt]);
                float h01 = bf_hi(h0h[nt]) + bf_hi(h0l[nt]);
                float h10 = bf_lo(h1h[nt]) + bf_lo(h1l[nt]);
                float h11 = bf_hi(h1h[nt]) + bf_hi(h1l[nt]);
                split_pair(ac3[nt][0] * (1.f - h00 * h00),
                           ac3[nt][1] * (1.f - h01 * h01), h0h[nt], h0l[nt]);
                split_pair(ac3[nt][2] * (1.f - h10 * h10),
                           ac3[nt][3] * (1.f - h11 * h11), h1h[nt], h1l[nt]);
            }
        }

        // ========== GEMM4: dEdD = G1 @ W1^T (N=64, K=128) =================
        {
            float ac4[8][4];
            #pragma unroll
            for (int nt = 0; nt < 8; nt++)
                #pragma unroll
                for (int q = 0; q < 4; q++) ac4[nt][q] = 0.f;

            #pragma unroll
            for (int s = 0; s < 8; s++) {
                uint32_t A0h = h0h[2 * s],     A0l = h0l[2 * s];
                uint32_t A1h = h1h[2 * s],     A1l = h1l[2 * s];
                uint32_t A2h = h0h[2 * s + 1], A2l = h0l[2 * s + 1];
                uint32_t A3h = h1h[2 * s + 1], A3l = h1l[2 * s + 1];
                #pragma unroll
                for (int nt = 0; nt < 8; nt++) {
                    uint2 B0 = W1TB[(8 * nt + g) * 68 + 8 * s + t];
                    uint2 B1 = W1TB[(8 * nt + g) * 68 + 8 * s + t + 4];
                    mma16(ac4[nt], A0h, A1h, A2h, A3h, B0.x, B1.x);
                    mma16(ac4[nt], A0l, A1l, A2l, A3l, B0.x, B1.x);
                    mma16(ac4[nt], A0h, A1h, A2h, A3h, B0.y, B1.y);
                }
            }
            // epi4: store dEdD
            #pragma unroll
            for (int nt = 0; nt < 8; nt++) {
                int c = 8 * nt + 2 * t;
                if (ok0)
                    *(float2*)(g_dEdD + (size_t)r0 * 64 + c)
                        = make_float2(ac4[nt][0], ac4[nt][1]);
                if (ok1)
                    *(float2*)(g_dEdD + (size_t)r1 * 64 + c)
                        = make_float2(ac4[nt][2], ac4[nt][3]);
            }
        }
    }
}

// ---------------------------------------------------------------------------
// Forces: 4 pairs per warp, 8-lane groups (proven: 120.8us, 86.2% DRAM)
// ---------------------------------------------------------------------------
__global__ void __launch_bounds__(256)
forces_kernel(const float* __restrict__ xd, const int* __restrict__ xd_indx,
              const int* __restrict__ uj, float* __restrict__ forces, int npairs)
{
    int w    = (blockIdx.x * blockDim.x + threadIdx.x) >> 5;
    int lane = threadIdx.x & 31;
    int li   = lane & 7;
    int pr   = lane >> 3;
    int p    = 4 * w + pr;
    if (4 * w >= npairs) return;
    bool valid = (p < npairs);
    int pc = valid ? p : (npairs - 1);

    int neigh = __ldg(xd_indx + 6 * pc);
    const float4* gp = (const float4*)(g_dEdD + (size_t)neigh * 64);
    float4 ga = gp[2 * li], gb = gp[2 * li + 1];

    const float4* xr = (const float4*)(xd + (size_t)pc * 192);
    float4 a0 = __ldcs(xr + 2 * li),      b0 = __ldcs(xr + 2 * li + 1);
    float4 a1 = __ldcs(xr + 16 + 2 * li), b1 = __ldcs(xr + 17 + 2 * li);
    float4 a2 = __ldcs(xr + 32 + 2 * li), b2 = __ldcs(xr + 33 + 2 * li);

    float s0 = a0.x*ga.x + a0.y*ga.y + a0.z*ga.z + a0.w*ga.w
             + b0.x*gb.x + b0.y*gb.y + b0.z*gb.z + b0.w*gb.w;
    float s1 = a1.x*ga.x + a1.y*ga.y + a1.z*ga.z + a1.w*ga.w
             + b1.x*gb.x + b1.y*gb.y + b1.z*gb.z + b1.w*gb.w;
    float s2 = a2.x*ga.x + a2.y*ga.y + a2.z*ga.z + a2.w*ga.w
             + b2.x*gb.x + b2.y*gb.y + b2.z*gb.z + b2.w*gb.w;

    #pragma unroll
    for (int off = 4; off; off >>= 1) {
        s0 += __shfl_xor_sync(0xffffffffu, s0, off);
        s1 += __shfl_xor_sync(0xffffffffu, s1, off);
        s2 += __shfl_xor_sync(0xffffffffu, s2, off);
    }
    if (li == 0 && valid) {
        int j0 = __ldg(uj + 3 * pc);
        int j1 = __ldg(uj + 3 * pc + 1);
        int j2 = __ldg(uj + 3 * pc + 2);
        atomicAdd(&forces[3 * j0 + 0], -s0);
        atomicAdd(&forces[3 * j1 + 1], -s1);
        atomicAdd(&forces[3 * j2 + 2], -s2);
    }
}

// ---------------------------------------------------------------------------
extern "C" void kernel_launch(void* const* d_in, const int* in_sizes, int n_in,
                              void* d_out, int out_size)
{
    const float* x       = (const float*)d_in[0];
    const float* xd      = (const float*)d_in[1];
    const int*   indices = (const int*)  d_in[2];
    const int*   xd_indx = (const int*)  d_in[4];
    const int*   uj      = (const int*)  d_in[5];
    const float* W1      = (const float*)d_in[6];
    const float* b1      = (const float*)d_in[7];
    const float* W2      = (const float*)d_in[8];
    const float* b2      = (const float*)d_in[9];
    const float* W3      = (const float*)d_in[10];
    const float* b3      = (const float*)d_in[11];
    float* out = (float*)d_out;

    int natoms  = in_sizes[0] / 64;    // 50000
    int nstruct = in_sizes[3];         // 250
    int npairs  = in_sizes[5] / 3;     // 1000000

    cudaMemsetAsync(out, 0, (size_t)out_size * sizeof(float), 0);

    cudaFuncSetAttribute(mlp_kernel, cudaFuncAttributeMaxDynamicSharedMemorySize,
                         SMEM_BYTES);
    mlp_kernel<<<148, 256, SMEM_BYTES>>>(x, indices, W1, b1, W2, b2, W3, b3,
                                         out, natoms);

    int nwarps = (npairs + 3) / 4;
    int blocks = (nwarps + 7) / 8;
    forces_kernel<<<blocks, 256>>>(xd, xd_indx, uj, out + nstruct, npairs);
}

// round 13
// speedup vs baseline: 1.3254x; 1.3254x over previous
#include <cuda_runtime.h>
#include <math.h>
#include <stdint.h>
#include <cuda_fp16.h>

#define MAX_ATOMS 50000

__device__ float g_dEdD[MAX_ATOMS * 64];
__device__ unsigned int g_chunk_ctr = 0;
__device__ unsigned int g_done_ctr  = 0;

// ---- smem byte-offset map (~177 KB) ----
// Weights: single fp16x2 packs (uint), strides 36/68 (≡4 mod 32 -> bank 4g+t,
// conflict-free full-warp LDS.32).
#define OB_W1B  0         // [t=128][dpair<32]  stride 36 u32 : B of GEMM1
#define OB_W2B  18432     // [j=64][tpair<64]   stride 68 u32 : B of GEMM2
#define OB_W2TB 35840     // [t=128][jpair<32]  stride 36 u32 : B of GEMM3
#define OB_W1TB 54272     // [d=64][tpair<64]   stride 68 u32 : B of GEMM4
#define OB_B1   71680
#define OB_B2   72192
#define OB_W3   72448
#define OB_H1   72704     // per-warp h1/g1: [16 rows][stride 68 uint2]
#define H1W_BYTES (16 * 68 * 8)     // 8704
#define NWARPS_CTA 12
#define SMEM_BYTES (OB_H1 + NWARPS_CTA * H1W_BYTES)   // 177152

// m16n8k16 fp16 mma, fp32 accumulate, D==C in place
__device__ __forceinline__ void mma16(float* d,
                                      uint32_t a0, uint32_t a1, uint32_t a2, uint32_t a3,
                                      uint32_t b0, uint32_t b1) {
    asm("mma.sync.aligned.m16n8k16.row.col.f32.f16.f16.f32 "
        "{%0,%1,%2,%3}, {%4,%5,%6,%7}, {%8,%9}, {%0,%1,%2,%3};"
        : "+f"(d[0]), "+f"(d[1]), "+f"(d[2]), "+f"(d[3])
        : "r"(a0), "r"(a1), "r"(a2), "r"(a3), "r"(b0), "r"(b1));
}
__device__ __forceinline__ uint32_t pack_f16(float v0, float v1) {
    __half2 h = __floats2half2_rn(v0, v1);      // lo=v0, hi=v1
    return *reinterpret_cast<uint32_t*>(&h);
}
// split pair -> fp16x2 hi pack + fp16x2 lo pack; v = hi + lo (~22-bit)
__device__ __forceinline__ void split_f16(float v0, float v1,
                                          uint32_t& hi, uint32_t& lo) {
    __half2 h = __floats2half2_rn(v0, v1);
    float r0 = v0 - __low2float(h);
    float r1 = v1 - __high2float(h);
    __half2 l = __floats2half2_rn(r0, r1);
    hi = *reinterpret_cast<uint32_t*>(&h);
    lo = *reinterpret_cast<uint32_t*>(&l);
}
__device__ __forceinline__ float f16_lo(uint32_t p) {
    __half2 h = *reinterpret_cast<__half2*>(&p); return __low2float(h);
}
__device__ __forceinline__ float f16_hi(uint32_t p) {
    __half2 h = *reinterpret_cast<__half2*>(&p); return __high2float(h);
}
// branch-free tanh: 1 - 2/(e^{2x}+1)
__device__ __forceinline__ float fast_tanh(float x) {
    float e, r;
    asm("ex2.approx.f32 %0, %1;" : "=f"(e) : "f"(x * 2.8853900817779268f));
    asm("rcp.approx.f32 %0, %1;" : "=f"(r) : "f"(e + 1.0f));
    return fmaf(-2.f, r, 1.f);
}

// ---------------------------------------------------------------------------
// MLP fwd+bwd, fp16 tensor cores, 2-mma compensation (A split, B single).
// 384 thr = 12 autonomous warps; 16 atoms/warp/chunk, ticket scheduler.
// ---------------------------------------------------------------------------
__global__ void __launch_bounds__(384, 1)
mlp_kernel(const float* __restrict__ x, const int* __restrict__ indices,
           const float* __restrict__ W1, const float* __restrict__ b1,
           const float* __restrict__ W2, const float* __restrict__ b2,
           const float* __restrict__ W3, const float* __restrict__ b3,
           float* __restrict__ energy, int natoms)
{
    extern __shared__ char smraw[];
    uint32_t* W1B  = (uint32_t*)(smraw + OB_W1B);
    uint32_t* W2B  = (uint32_t*)(smraw + OB_W2B);
    uint32_t* W2TB = (uint32_t*)(smraw + OB_W2TB);
    uint32_t* W1TB = (uint32_t*)(smraw + OB_W1TB);
    float* b1s  = (float*)(smraw + OB_B1);
    float* b2s  = (float*)(smraw + OB_B2);
    float* w3s  = (float*)(smraw + OB_W3);

    const int tid  = threadIdx.x;
    const int wid  = tid >> 5;
    const int lane = tid & 31;

    // ---- stage weights: single fp16x2 packs, 4 layouts ----
    for (int i = tid; i < 128 * 32; i += 384) {       // W1B [t][dpair]
        int t = i >> 5, dp = i & 31;
        W1B[t * 36 + dp] = pack_f16(W1[(2 * dp) * 128 + t], W1[(2 * dp + 1) * 128 + t]);
    }
    for (int i = tid; i < 64 * 64; i += 384) {        // W2B [j][tpair]
        int j = i >> 6, tp = i & 63;
        W2B[j * 68 + tp] = pack_f16(W2[(2 * tp) * 64 + j], W2[(2 * tp + 1) * 64 + j]);
    }
    for (int i = tid; i < 128 * 32; i += 384) {       // W2TB [t][jpair]
        int t = i >> 5, jp = i & 31;
        W2TB[t * 36 + jp] = pack_f16(W2[t * 64 + 2 * jp], W2[t * 64 + 2 * jp + 1]);
    }
    for (int i = tid; i < 64 * 64; i += 384) {        // W1TB [d][tpair]
        int d = i >> 6, tp = i & 63;
        W1TB[d * 68 + tp] = pack_f16(W1[d * 128 + 2 * tp], W1[d * 128 + 2 * tp + 1]);
    }
    if (tid < 128) b1s[tid] = b1[tid];
    if (tid < 64)  { b2s[tid] = b2[tid]; w3s[tid] = W3[tid]; }
    const float b3v = b3[0];
    __syncthreads();

    uint2* h1p = (uint2*)(smraw + OB_H1 + wid * H1W_BYTES);   // [16][stride 68]
    const int g = lane >> 2;     // groupID 0..7
    const int t = lane & 3;      // threadID in group

    const int nchunk = (natoms + 15) >> 4;
    const int total_warps = gridDim.x * NWARPS_CTA;
    const float2* x2 = (const float2*)x;

    for (;;) {
        unsigned int chunk;
        if (lane == 0) chunk = atomicAdd(&g_chunk_ctr, 1u);
        chunk = __shfl_sync(0xffffffffu, chunk, 0);
        if (chunk >= (unsigned)nchunk) break;

        const int base = (int)chunk << 4;
        const int r0 = base + g, r1 = base + g + 8;
        const bool ok0 = r0 < natoms, ok1 = r1 < natoms;

        // ========== GEMM1: H1pre = X @ W1  (N=128, K=64) ==================
        {
            float acc[16][4];
            #pragma unroll
            for (int nt = 0; nt < 16; nt++)
                #pragma unroll
                for (int q = 0; q < 4; q++) acc[nt][q] = 0.f;

            #pragma unroll 1
            for (int s = 0; s < 4; s++) {
                float2 z = make_float2(0.f, 0.f);
                float2 v00 = ok0 ? __ldg(x2 + (size_t)r0 * 32 + 8 * s + t)     : z;
                float2 v01 = ok0 ? __ldg(x2 + (size_t)r0 * 32 + 8 * s + t + 4) : z;
                float2 v10 = ok1 ? __ldg(x2 + (size_t)r1 * 32 + 8 * s + t)     : z;
                float2 v11 = ok1 ? __ldg(x2 + (size_t)r1 * 32 + 8 * s + t + 4) : z;
                uint32_t a0h, a0l, a1h, a1l, a2h, a2l, a3h, a3l;
                split_f16(v00.x, v00.y, a0h, a0l);
                split_f16(v10.x, v10.y, a1h, a1l);
                split_f16(v01.x, v01.y, a2h, a2l);
                split_f16(v11.x, v11.y, a3h, a3l);
                #pragma unroll
                for (int nt = 0; nt < 16; nt++) {
                    uint32_t B0 = W1B[(8 * nt + g) * 36 + 8 * s + t];
                    uint32_t B1 = W1B[(8 * nt + g) * 36 + 8 * s + t + 4];
                    mma16(acc[nt], a0h, a1h, a2h, a3h, B0, B1);
                    mma16(acc[nt], a0l, a1l, a2l, a3l, B0, B1);
                }
            }
            // epi1: h1 = tanh(.+b1) -> h1p as {hi,lo} fp16 packs
            #pragma unroll
            for (int nt = 0; nt < 16; nt++) {
                int c = 8 * nt + 2 * t;
                float2 bb = *(const float2*)(b1s + c);
                uint32_t hi, lo;
                split_f16(fast_tanh(acc[nt][0] + bb.x),
                          fast_tanh(acc[nt][1] + bb.y), hi, lo);
                h1p[g * 68 + 4 * nt + t] = make_uint2(hi, lo);
                split_f16(fast_tanh(acc[nt][2] + bb.x),
                          fast_tanh(acc[nt][3] + bb.y), hi, lo);
                h1p[(g + 8) * 68 + 4 * nt + t] = make_uint2(hi, lo);
            }
        }
        __syncwarp();

        // ========== GEMM2: H2pre = H1 @ W2 (N=64, K=128) ==================
        float d2v[8][4];
        float e0 = 0.f, e1 = 0.f;
        {
            float ac2[8][4];
            #pragma unroll
            for (int nt = 0; nt < 8; nt++)
                #pragma unroll
                for (int q = 0; q < 4; q++) ac2[nt][q] = 0.f;

            #pragma unroll 1
            for (int s = 0; s < 8; s++) {
                uint2 A0 = h1p[g * 68 + 8 * s + t];
                uint2 A1 = h1p[(g + 8) * 68 + 8 * s + t];
                uint2 A2 = h1p[g * 68 + 8 * s + t + 4];
                uint2 A3 = h1p[(g + 8) * 68 + 8 * s + t + 4];
                #pragma unroll
                for (int nt = 0; nt < 8; nt++) {
                    uint32_t B0 = W2B[(8 * nt + g) * 68 + 8 * s + t];
                    uint32_t B1 = W2B[(8 * nt + g) * 68 + 8 * s + t + 4];
                    mma16(ac2[nt], A0.x, A1.x, A2.x, A3.x, B0, B1);
                    mma16(ac2[nt], A0.y, A1.y, A2.y, A3.y, B0, B1);
                }
            }
            // epi2: h2 = tanh(.+b2); energy; d2 = w3*(1-h2^2)
            #pragma unroll
            for (int nt = 0; nt < 8; nt++) {
                int c = 8 * nt + 2 * t;
                float2 bb = *(const float2*)(b2s + c);
                float2 w3 = *(const float2*)(w3s + c);
                float h0 = fast_tanh(ac2[nt][0] + bb.x);
                float h1v = fast_tanh(ac2[nt][1] + bb.y);
                float h2v = fast_tanh(ac2[nt][2] + bb.x);
                float h3v = fast_tanh(ac2[nt][3] + bb.y);
                e0 += h0 * w3.x + h1v * w3.y;
                e1 += h2v * w3.x + h3v * w3.y;
                d2v[nt][0] = w3.x * (1.f - h0 * h0);
                d2v[nt][1] = w3.y * (1.f - h1v * h1v);
                d2v[nt][2] = w3.x * (1.f - h2v * h2v);
                d2v[nt][3] = w3.y * (1.f - h3v * h3v);
            }
        }
        e0 += __shfl_xor_sync(0xffffffffu, e0, 1);
        e0 += __shfl_xor_sync(0xffffffffu, e0, 2);
        e1 += __shfl_xor_sync(0xffffffffu, e1, 1);
        e1 += __shfl_xor_sync(0xffffffffu, e1, 2);
        if (t == 0) {
            if (ok0) atomicAdd(&energy[__ldg(indices + r0)], e0 + b3v);
            if (ok1) atomicAdd(&energy[__ldg(indices + r1)], e1 + b3v);
        }

        // ========== GEMM3: G1pre = D2 @ W2^T (N=128, K=64) ================
        {
            float ac3[16][4];
            #pragma unroll
            for (int nt = 0; nt < 16; nt++)
                #pragma unroll
                for (int q = 0; q < 4; q++) ac3[nt][q] = 0.f;

            #pragma unroll 1
            for (int s = 0; s < 4; s++) {
                uint32_t a0h, a0l, a1h, a1l, a2h, a2l, a3h, a3l;
                split_f16(d2v[2 * s][0],     d2v[2 * s][1],     a0h, a0l);
                split_f16(d2v[2 * s][2],     d2v[2 * s][3],     a1h, a1l);
                split_f16(d2v[2 * s + 1][0], d2v[2 * s + 1][1], a2h, a2l);
                split_f16(d2v[2 * s + 1][2], d2v[2 * s + 1][3], a3h, a3l);
                #pragma unroll
                for (int nt = 0; nt < 16; nt++) {
                    uint32_t B0 = W2TB[(8 * nt + g) * 36 + 8 * s + t];
                    uint32_t B1 = W2TB[(8 * nt + g) * 36 + 8 * s + t + 4];
                    mma16(ac3[nt], a0h, a1h, a2h, a3h, B0, B1);
                    mma16(ac3[nt], a0l, a1l, a2l, a3l, B0, B1);
                }
            }
            // epi3: g1 = G1pre * (1 - h1^2), in place over h1p
            #pragma unroll
            for (int nt = 0; nt < 16; nt++) {
                uint2* p0 = h1p + g * 68 + 4 * nt + t;
                uint2* p1 = h1p + (g + 8) * 68 + 4 * nt + t;
                uint2 u0 = *p0, u1 = *p1;
                float h00 = f16_lo(u0.x) + f16_lo(u0.y);
                float h01 = f16_hi(u0.x) + f16_hi(u0.y);
                float h10 = f16_lo(u1.x) + f16_lo(u1.y);
                float h11 = f16_hi(u1.x) + f16_hi(u1.y);
                uint32_t hi, lo;
                split_f16(ac3[nt][0] * (1.f - h00 * h00),
                          ac3[nt][1] * (1.f - h01 * h01), hi, lo);
                *p0 = make_uint2(hi, lo);
                split_f16(ac3[nt][2] * (1.f - h10 * h10),
                          ac3[nt][3] * (1.f - h11 * h11), hi, lo);
                *p1 = make_uint2(hi, lo);
            }
        }
        __syncwarp();

        // ========== GEMM4: dEdD = G1 @ W1^T (N=64, K=128) =================
        {
            float ac4[8][4];
            #pragma unroll
            for (int nt = 0; nt < 8; nt++)
                #pragma unroll
                for (int q = 0; q < 4; q++) ac4[nt][q] = 0.f;

            #pragma unroll 1
            for (int s = 0; s < 8; s++) {
                uint2 A0 = h1p[g * 68 + 8 * s + t];
                uint2 A1 = h1p[(g + 8) * 68 + 8 * s + t];
                uint2 A2 = h1p[g * 68 + 8 * s + t + 4];
                uint2 A3 = h1p[(g + 8) * 68 + 8 * s + t + 4];
                #pragma unroll
                for (int nt = 0; nt < 8; nt++) {
                    uint32_t B0 = W1TB[(8 * nt + g) * 68 + 8 * s + t];
                    uint32_t B1 = W1TB[(8 * nt + g) * 68 + 8 * s + t + 4];
                    mma16(ac4[nt], A0.x, A1.x, A2.x, A3.x, B0, B1);
                    mma16(ac4[nt], A0.y, A1.y, A2.y, A3.y, B0, B1);
                }
            }
            // epi4: store dEdD
            #pragma unroll
            for (int nt = 0; nt < 8; nt++) {
                int c = 8 * nt + 2 * t;
                if (ok0)
                    *(float2*)(g_dEdD + (size_t)r0 * 64 + c)
                        = make_float2(ac4[nt][0], ac4[nt][1]);
                if (ok1)
                    *(float2*)(g_dEdD + (size_t)r1 * 64 + c)
                        = make_float2(ac4[nt][2], ac4[nt][3]);
            }
        }
        __syncwarp();
    }

    // ---- self-reset ticket counter for next graph replay ----
    if (lane == 0) {
        __threadfence();
        unsigned int d = atomicAdd(&g_done_ctr, 1u);
        if (d == (unsigned)(total_warps - 1)) {
            g_chunk_ctr = 0;
            g_done_ctr  = 0;
            __threadfence();
        }
    }
}

// ---------------------------------------------------------------------------
// Forces: 4 pairs per warp, 8-lane groups (proven: 120.8us, 86.2% DRAM)
// ---------------------------------------------------------------------------
__global__ void __launch_bounds__(256)
forces_kernel(const float* __restrict__ xd, const int* __restrict__ xd_indx,
              const int* __restrict__ uj, float* __restrict__ forces, int npairs)
{
    int w    = (blockIdx.x * blockDim.x + threadIdx.x) >> 5;
    int lane = threadIdx.x & 31;
    int li   = lane & 7;
    int pr   = lane >> 3;
    int p    = 4 * w + pr;
    if (4 * w >= npairs) return;
    bool valid = (p < npairs);
    int pc = valid ? p : (npairs - 1);

    int neigh = __ldg(xd_indx + 6 * pc);
    const float4* gp = (const float4*)(g_dEdD + (size_t)neigh * 64);
    float4 ga = gp[2 * li], gb = gp[2 * li + 1];

    const float4* xr = (const float4*)(xd + (size_t)pc * 192);
    float4 a0 = __ldcs(xr + 2 * li),      b0 = __ldcs(xr + 2 * li + 1);
    float4 a1 = __ldcs(xr + 16 + 2 * li), b1 = __ldcs(xr + 17 + 2 * li);
    float4 a2 = __ldcs(xr + 32 + 2 * li), b2 = __ldcs(xr + 33 + 2 * li);

    float s0 = a0.x*ga.x + a0.y*ga.y + a0.z*ga.z + a0.w*ga.w
             + b0.x*gb.x + b0.y*gb.y + b0.z*gb.z + b0.w*gb.w;
    float s1 = a1.x*ga.x + a1.y*ga.y + a1.z*ga.z + a1.w*ga.w
             + b1.x*gb.x + b1.y*gb.y + b1.z*gb.z + b1.w*gb.w;
    float s2 = a2.x*ga.x + a2.y*ga.y + a2.z*ga.z + a2.w*ga.w
             + b2.x*gb.x + b2.y*gb.y + b2.z*gb.z + b2.w*gb.w;

    #pragma unroll
    for (int off = 4; off; off >>= 1) {
        s0 += __shfl_xor_sync(0xffffffffu, s0, off);
        s1 += __shfl_xor_sync(0xffffffffu, s1, off);
        s2 += __shfl_xor_sync(0xffffffffu, s2, off);
    }
    if (li == 0 && valid) {
        int j0 = __ldg(uj + 3 * pc);
        int j1 = __ldg(uj + 3 * pc + 1);
        int j2 = __ldg(uj + 3 * pc + 2);
        atomicAdd(&forces[3 * j0 + 0], -s0);
        atomicAdd(&forces[3 * j1 + 1], -s1);
        atomicAdd(&forces[3 * j2 + 2], -s2);
    }
}

// ---------------------------------------------------------------------------
extern "C" void kernel_launch(void* const* d_in, const int* in_sizes, int n_in,
                              void* d_out, int out_size)
{
    const float* x       = (const float*)d_in[0];
    const float* xd      = (const float*)d_in[1];
    const int*   indices = (const int*)  d_in[2];
    const int*   xd_indx = (const int*)  d_in[4];
    const int*   uj      = (const int*)  d_in[5];
    const float* W1      = (const float*)d_in[6];
    const float* b1      = (const float*)d_in[7];
    const float* W2      = (const float*)d_in[8];
    const float* b2      = (const float*)d_in[9];
    const float* W3      = (const float*)d_in[10];
    const float* b3      = (const float*)d_in[11];
    float* out = (float*)d_out;

    int natoms  = in_sizes[0] / 64;    // 50000
    int nstruct = in_sizes[3];         // 250
    int npairs  = in_sizes[5] / 3;     // 1000000

    cudaMemsetAsync(out, 0, (size_t)out_size * sizeof(float), 0);

    cudaFuncSetAttribute(mlp_kernel, cudaFuncAttributeMaxDynamicSharedMemorySize,
                         SMEM_BYTES);
    mlp_kernel<<<148, 384, SMEM_BYTES>>>(x, indices, W1, b1, W2, b2, W3, b3,
                                         out, natoms);

    int nwarps = (npairs + 3) / 4;
    int blocks = (nwarps + 7) / 8;
    forces_kernel<<<blocks, 256>>>(xd, xd_indx, uj, out + nstruct, npairs);
}